// round 4
// baseline (speedup 1.0000x reference)
#include <cuda_runtime.h>

// P=50000, H=W=28, CARD=50
// Inputs: p[50000] f32, I[784*50000] f32, J[784*50000] f32,
//         inds1[100*2] i32, inds2[100*2] i32
// Output: 200 f32 (dgm1 flat [100] then dgm2 flat [100])

#define P_DIM    50000
#define W_IMG    28
#define N_OUT    200
#define ROW_F4   (P_DIM / 4)              // 12500 float4 per row
#define W_TOT    ((long long)N_OUT * ROW_F4)  // 2,500,000 float4 total
#define NTHREADS 256
#define GRID     592                      // 4 * 148 SMs -> one even wave

__device__ float g_val[2 * GRID];
__device__ int   g_oid[2 * GRID];
__device__ unsigned int g_done = 0;

__device__ __forceinline__ float block_reduce(float v, float* ws) {
    #pragma unroll
    for (int off = 16; off > 0; off >>= 1)
        v += __shfl_down_sync(0xffffffffu, v, off);
    if ((threadIdx.x & 31) == 0) ws[threadIdx.x >> 5] = v;
    __syncthreads();
    float r = 0.0f;
    if (threadIdx.x < (NTHREADS / 32)) r = ws[threadIdx.x];
    if (threadIdx.x < 32) {
        #pragma unroll
        for (int off = (NTHREADS / 64); off > 0; off >>= 1)
            r += __shfl_down_sync(0xffu, r, off);
    }
    __syncthreads();
    return r;  // valid in thread 0
}

__global__ __launch_bounds__(NTHREADS, 4)
void fused_flat_dot(const float* __restrict__ p,
                    const float* __restrict__ I,
                    const float* __restrict__ J,
                    const int*   __restrict__ inds1,
                    const int*   __restrict__ inds2,
                    float*       __restrict__ out) {
    const int b   = blockIdx.x;
    const int tid = threadIdx.x;

    // exactly-even flat range of float4 work items
    const long long lo = (long long)b       * W_TOT / GRID;
    const long long hi = (long long)(b + 1) * W_TOT / GRID;

    const int r0 = (int)(lo / ROW_F4);            // first output id
    const int r1 = (int)((hi - 1) / ROW_F4);      // last output id (r0 or r0+1)

    const float4* p4 = reinterpret_cast<const float4*>(p);

    __shared__ float ws[NTHREADS / 32];
    __shared__ bool  s_last;

    float seg_sum[2] = {0.0f, 0.0f};
    int   seg_oid[2] = {-1, -1};

    #pragma unroll
    for (int s = 0; s < 2; s++) {
        int o = (s == 0) ? r0 : r1;
        if (s == 1 && r1 == r0) break;
        long long seg_lo = (s == 0) ? lo : (long long)o * ROW_F4;
        long long seg_hi = (s == 0) ? ((r1 != r0) ? (long long)(r0 + 1) * ROW_F4 : hi) : hi;

        // map output id -> gathered matrix row
        const float* mat; const int* inds; int j;
        if (o < 100) { mat = I; inds = inds1; j = o; }
        else         { mat = J; inds = inds2; j = o - 100; }
        int rr = inds[2 * j + 0];
        int cc = inds[2 * j + 1];
        const float4* m4 = reinterpret_cast<const float4*>(mat) +
                           (size_t)(rr * W_IMG + cc) * ROW_F4;

        const int base = (int)(seg_lo - (long long)o * ROW_F4);  // within-row f4 offset
        const int len  = (int)(seg_hi - seg_lo);

        float acc = 0.0f;
        #pragma unroll 8
        for (int i = tid; i < len; i += NTHREADS) {
            float4 a = m4[base + i];
            float4 q = p4[base + i];
            acc += a.x * q.x + a.y * q.y + a.z * q.z + a.w * q.w;
        }
        seg_sum[s] = acc;
        seg_oid[s] = o;
    }

    // two block reductions (second is trivial if unused)
    float t0 = block_reduce(seg_sum[0], ws);
    float t1 = block_reduce(seg_sum[1], ws);
    if (tid == 0) {
        g_val[2 * b + 0] = t0;  g_oid[2 * b + 0] = seg_oid[0];
        g_val[2 * b + 1] = t1;  g_oid[2 * b + 1] = seg_oid[1];
        __threadfence();
        unsigned int prev = atomicAdd(&g_done, 1u);
        s_last = (prev == GRID - 1);
    }
    __syncthreads();

    if (s_last) {
        __shared__ float acc[N_OUT];
        for (int i = tid; i < N_OUT; i += NTHREADS) acc[i] = 0.0f;
        __syncthreads();
        for (int i = tid; i < 2 * GRID; i += NTHREADS) {
            int o = g_oid[i];
            if (o >= 0) atomicAdd(&acc[o], g_val[i]);
        }
        __syncthreads();
        for (int i = tid; i < N_OUT; i += NTHREADS) out[i] = acc[i];
        if (tid == 0) g_done = 0;
    }
}

extern "C" void kernel_launch(void* const* d_in, const int* in_sizes, int n_in,
                              void* d_out, int out_size) {
    const float* p     = (const float*)d_in[0];
    const float* I     = (const float*)d_in[1];
    const float* J     = (const float*)d_in[2];
    const int*   inds1 = (const int*)d_in[3];
    const int*   inds2 = (const int*)d_in[4];
    float* out = (float*)d_out;

    fused_flat_dot<<<GRID, NTHREADS>>>(p, I, J, inds1, inds2, out);
}

// round 5
// speedup vs baseline: 1.3017x; 1.3017x over previous
#include <cuda_runtime.h>

// P=50000, H=W=28, CARD=50
// Inputs: p[50000] f32, I[784*50000] f32, J[784*50000] f32,
//         inds1[100*2] i32, inds2[100*2] i32
// Output: 200 f32 (dgm1 flat [100] then dgm2 flat [100])

#define P_DIM   50000
#define W_IMG   28
#define N_OUT   200
#define SPLIT   4
#define CHUNK   (P_DIM / SPLIT)     // 12500 floats
#define CHUNK4  (CHUNK / 4)         // 3125 float4
#define NTHREADS 256
#define NBLOCKS (N_OUT * SPLIT)     // 800

__device__ float g_partial[N_OUT * SPLIT];
__device__ unsigned int g_done = 0;

__global__ __launch_bounds__(NTHREADS, 5)
void fused_gathered_dot(const float* __restrict__ p,
                        const float* __restrict__ I,
                        const float* __restrict__ J,
                        const int*   __restrict__ inds1,
                        const int*   __restrict__ inds2,
                        float*       __restrict__ out) {
    int b = blockIdx.x;          // 0 .. 799
    int o = b >> 2;              // output index 0..199
    int c = b & (SPLIT - 1);     // K-chunk 0..3

    const float* mat;
    const int*   inds;
    int j;
    if (o < 100) { mat = I; inds = inds1; j = o; }
    else         { mat = J; inds = inds2; j = o - 100; }

    int r  = inds[2 * j + 0];
    int cc = inds[2 * j + 1];
    const float4* row4 = reinterpret_cast<const float4*>(
        mat + (size_t)(r * W_IMG + cc) * P_DIM + c * CHUNK);
    const float4* p4 = reinterpret_cast<const float4*>(p + c * CHUNK);

    float sum = 0.0f;
    #pragma unroll 8
    for (int i = threadIdx.x; i < CHUNK4; i += NTHREADS) {
        float4 a = __ldcs(&row4[i]);   // streaming: no reuse, evict-first
        float4 q = __ldg(&p4[i]);      // hot in L2 (reused by all blocks)
        sum += a.x * q.x + a.y * q.y + a.z * q.z + a.w * q.w;
    }

    // intra-block reduction
    #pragma unroll
    for (int off = 16; off > 0; off >>= 1)
        sum += __shfl_down_sync(0xffffffffu, sum, off);

    __shared__ float ws[NTHREADS / 32];
    __shared__ bool  s_last;
    if ((threadIdx.x & 31) == 0) ws[threadIdx.x >> 5] = sum;
    __syncthreads();

    if (threadIdx.x < (NTHREADS / 32)) {
        float v = ws[threadIdx.x];
        #pragma unroll
        for (int off = (NTHREADS / 64); off > 0; off >>= 1)
            v += __shfl_down_sync(0xffu, v, off);
        if (threadIdx.x == 0) g_partial[o * SPLIT + c] = v;
    }

    // last finishing block reduces 800 partials -> 200 outputs
    if (threadIdx.x == 0) {
        __threadfence();
        unsigned int prev = atomicAdd(&g_done, 1u);
        s_last = (prev == NBLOCKS - 1);
    }
    __syncthreads();

    if (s_last) {
        int oo = threadIdx.x;
        if (oo < N_OUT) {
            float s = 0.0f;
            #pragma unroll
            for (int k = 0; k < SPLIT; k++) s += g_partial[oo * SPLIT + k];
            out[oo] = s;
        }
        if (threadIdx.x == 0) g_done = 0;   // reset for next graph replay
    }
}

extern "C" void kernel_launch(void* const* d_in, const int* in_sizes, int n_in,
                              void* d_out, int out_size) {
    const float* p     = (const float*)d_in[0];
    const float* I     = (const float*)d_in[1];
    const float* J     = (const float*)d_in[2];
    const int*   inds1 = (const int*)d_in[3];
    const int*   inds2 = (const int*)d_in[4];
    float* out = (float*)d_out;

    fused_gathered_dot<<<NBLOCKS, NTHREADS>>>(p, I, J, inds1, inds2, out);
}

// round 6
// speedup vs baseline: 1.3375x; 1.0275x over previous
#include <cuda_runtime.h>

// P=50000, H=W=28, CARD=50
// Inputs: p[50000] f32, I[784*50000] f32, J[784*50000] f32,
//         inds1[100*2] i32, inds2[100*2] i32
// Output: 200 f32 (dgm1 flat [100] then dgm2 flat [100])

#define P_DIM   50000
#define W_IMG   28
#define N_OUT   200
#define SPLIT   10
#define CHUNK   (P_DIM / SPLIT)     // 5000 floats
#define CHUNK4  (CHUNK / 4)         // 1250 float4
#define NTHREADS 256
#define NBLOCKS (N_OUT * SPLIT)     // 2000

__device__ float g_partial[N_OUT * SPLIT];
__device__ unsigned int g_done = 0;

__global__ __launch_bounds__(NTHREADS)
void fused_gathered_dot(const float* __restrict__ p,
                        const float* __restrict__ I,
                        const float* __restrict__ J,
                        const int*   __restrict__ inds1,
                        const int*   __restrict__ inds2,
                        float*       __restrict__ out) {
    int b = blockIdx.x;          // 0 .. NBLOCKS-1
    int o = b / SPLIT;           // output index 0..199
    int c = b % SPLIT;           // K-chunk 0..SPLIT-1

    const float* mat;
    const int*   inds;
    int j;
    if (o < 100) { mat = I; inds = inds1; j = o; }
    else         { mat = J; inds = inds2; j = o - 100; }

    int r  = inds[2 * j + 0];
    int cc = inds[2 * j + 1];
    const float4* row4 = reinterpret_cast<const float4*>(
        mat + (size_t)(r * W_IMG + cc) * P_DIM + c * CHUNK);
    const float4* p4 = reinterpret_cast<const float4*>(p + c * CHUNK);

    float sum = 0.0f;
    #pragma unroll 4
    for (int i = threadIdx.x; i < CHUNK4; i += NTHREADS) {
        float4 a = row4[i];
        float4 q = p4[i];
        sum += a.x * q.x + a.y * q.y + a.z * q.z + a.w * q.w;
    }

    // intra-block reduction
    #pragma unroll
    for (int off = 16; off > 0; off >>= 1)
        sum += __shfl_down_sync(0xffffffffu, sum, off);

    __shared__ float ws[NTHREADS / 32];
    __shared__ bool  s_last;
    if ((threadIdx.x & 31) == 0) ws[threadIdx.x >> 5] = sum;
    __syncthreads();

    if (threadIdx.x < (NTHREADS / 32)) {
        float v = ws[threadIdx.x];
        #pragma unroll
        for (int off = (NTHREADS / 64); off > 0; off >>= 1)
            v += __shfl_down_sync(0xffu, v, off);
        if (threadIdx.x == 0) g_partial[o * SPLIT + c] = v;
    }

    // last finishing block reduces NBLOCKS partials -> 200 outputs
    if (threadIdx.x == 0) {
        __threadfence();
        unsigned int prev = atomicAdd(&g_done, 1u);
        s_last = (prev == NBLOCKS - 1);
    }
    __syncthreads();

    if (s_last) {
        int oo = threadIdx.x;
        if (oo < N_OUT) {
            float s = 0.0f;
            #pragma unroll
            for (int k = 0; k < SPLIT; k++) s += g_partial[oo * SPLIT + k];
            out[oo] = s;
        }
        if (threadIdx.x == 0) g_done = 0;   // reset for next graph replay
    }
}

extern "C" void kernel_launch(void* const* d_in, const int* in_sizes, int n_in,
                              void* d_out, int out_size) {
    const float* p     = (const float*)d_in[0];
    const float* I     = (const float*)d_in[1];
    const float* J     = (const float*)d_in[2];
    const int*   inds1 = (const int*)d_in[3];
    const int*   inds2 = (const int*)d_in[4];
    float* out = (float*)d_out;

    fused_gathered_dot<<<NBLOCKS, NTHREADS>>>(p, I, J, inds1, inds2, out);
}

// round 7
// speedup vs baseline: 1.5598x; 1.1662x over previous
#include <cuda_runtime.h>

// P=50000, H=W=28, CARD=50
// Inputs: p[50000] f32, I[784*50000] f32, J[784*50000] f32,
//         inds1[100*2] i32, inds2[100*2] i32
// Output: 200 f32

#define P_DIM    50000
#define W_IMG    28
#define N_OUT    200
#define ROW_F4   (P_DIM / 4)        // 12500 float4 per row
#define RPB      4                  // rows (outputs) per block
#define NGROUPS  (N_OUT / RPB)      // 50
#define SPLIT    12                 // K-chunks per group
#define NBLOCKS  (NGROUPS * SPLIT)  // 600  (~4.05 CTA/SM)
#define NTHREADS 256

__device__ float g_partial[N_OUT * SPLIT];
__device__ unsigned int g_done = 0;

__device__ __forceinline__ float block_reduce(float v, float* ws) {
    #pragma unroll
    for (int off = 16; off > 0; off >>= 1)
        v += __shfl_down_sync(0xffffffffu, v, off);
    if ((threadIdx.x & 31) == 0) ws[threadIdx.x >> 5] = v;
    __syncthreads();
    float r = 0.0f;
    if (threadIdx.x < (NTHREADS / 32)) r = ws[threadIdx.x];
    if (threadIdx.x < 32) {
        #pragma unroll
        for (int off = (NTHREADS / 64); off > 0; off >>= 1)
            r += __shfl_down_sync(0xffu, r, off);
    }
    __syncthreads();
    return r;   // valid in thread 0
}

__global__ __launch_bounds__(NTHREADS)
void fused_multi_dot(const float* __restrict__ p,
                     const float* __restrict__ I,
                     const float* __restrict__ J,
                     const int*   __restrict__ inds1,
                     const int*   __restrict__ inds2,
                     float*       __restrict__ out) {
    const int b   = blockIdx.x;
    const int g   = b / SPLIT;      // output group 0..49  (outputs 4g..4g+3)
    const int c   = b % SPLIT;      // K-chunk
    const int tid = threadIdx.x;

    // group -> matrix + index table (groups never straddle I/J since 100 = 4*25)
    const float* mat;
    const int*   inds;
    int jbase;
    if (g < NGROUPS / 2) { mat = I; inds = inds1; jbase = g * RPB; }
    else                 { mat = J; inds = inds2; jbase = g * RPB - 100; }

    const float4* r4[RPB];
    #pragma unroll
    for (int u = 0; u < RPB; u++) {
        int j  = jbase + u;
        int rr = inds[2 * j + 0];
        int cc = inds[2 * j + 1];
        r4[u] = reinterpret_cast<const float4*>(mat) +
                (size_t)(rr * W_IMG + cc) * ROW_F4;
    }
    const float4* p4 = reinterpret_cast<const float4*>(p);

    // generic chunk bounds in float4 units (handles 12500 % 12 != 0)
    const int start = (c * ROW_F4) / SPLIT;
    const int end   = ((c + 1) * ROW_F4) / SPLIT;

    float a0 = 0.0f, a1 = 0.0f, a2 = 0.0f, a3 = 0.0f;
    #pragma unroll 2
    for (int i = start + tid; i < end; i += NTHREADS) {
        float4 q  = p4[i];
        float4 v0 = r4[0][i];
        float4 v1 = r4[1][i];
        float4 v2 = r4[2][i];
        float4 v3 = r4[3][i];
        a0 += v0.x * q.x + v0.y * q.y + v0.z * q.z + v0.w * q.w;
        a1 += v1.x * q.x + v1.y * q.y + v1.z * q.z + v1.w * q.w;
        a2 += v2.x * q.x + v2.y * q.y + v2.z * q.z + v2.w * q.w;
        a3 += v3.x * q.x + v3.y * q.y + v3.z * q.z + v3.w * q.w;
    }

    __shared__ float ws[NTHREADS / 32];
    __shared__ bool  s_last;

    float t0 = block_reduce(a0, ws);
    float t1 = block_reduce(a1, ws);
    float t2 = block_reduce(a2, ws);
    float t3 = block_reduce(a3, ws);

    if (tid == 0) {
        int ob = g * RPB;
        g_partial[(ob + 0) * SPLIT + c] = t0;
        g_partial[(ob + 1) * SPLIT + c] = t1;
        g_partial[(ob + 2) * SPLIT + c] = t2;
        g_partial[(ob + 3) * SPLIT + c] = t3;
        __threadfence();
        unsigned int prev = atomicAdd(&g_done, 1u);
        s_last = (prev == NBLOCKS - 1);
    }
    __syncthreads();

    if (s_last) {
        int oo = tid;
        if (oo < N_OUT) {
            float s = 0.0f;
            #pragma unroll
            for (int k = 0; k < SPLIT; k++) s += g_partial[oo * SPLIT + k];
            out[oo] = s;
        }
        if (tid == 0) g_done = 0;   // reset for next graph replay
    }
}

extern "C" void kernel_launch(void* const* d_in, const int* in_sizes, int n_in,
                              void* d_out, int out_size) {
    const float* p     = (const float*)d_in[0];
    const float* I     = (const float*)d_in[1];
    const float* J     = (const float*)d_in[2];
    const int*   inds1 = (const int*)d_in[3];
    const int*   inds2 = (const int*)d_in[4];
    float* out = (float*)d_out;

    fused_multi_dot<<<NBLOCKS, NTHREADS>>>(p, I, J, inds1, inds2, out);
}